// round 2
// baseline (speedup 1.0000x reference)
#include <cuda_runtime.h>
#include <cstring>
#include <math.h>

#define S_  1024
#define B_  64
#define H_  1024
#define E_  512
#define V_  32000
#define EH_ 1536

typedef unsigned long long ull;

// ---------------- scratch (device globals; no runtime allocation) -------------
__device__ float g_x[B_*H_];        // input-context projection x [B,H]
__device__ float g_base[B_*H_];     // Wah@h_new + bah + bas + bac  [B,H]
__device__ float g_scores[B_*S_];   // attention scores [B,S]
__device__ float g_attn[B_*S_];     // renormalized attention [B,S]
__device__ float g_logits[B_*V_];   // vocab logits (8 MB)

// ---------------- output layout (f32, concatenated in return order) ----------
#define OFF_PGEN  0
#define OFF_VOCAB 64
#define OFF_HNEW  (OFF_VOCAB + B_*V_)
#define OFF_CTX   (OFF_HNEW + B_*H_)
#define OFF_ATTN  (OFF_CTX  + B_*H_)
#define OFF_COV   (OFF_ATTN + B_*S_)

// ---------------- helpers ----------------------------------------------------
__device__ __forceinline__ void ffma2(ull& acc, ull a, ull b) {
    asm("fma.rn.f32x2 %0, %1, %2, %0;" : "+l"(acc) : "l"(a), "l"(b));
}
__device__ __forceinline__ ull pk2(float x, float y) {
    float2 f = make_float2(x, y); ull u; memcpy(&u, &f, 8); return u;
}
__device__ __forceinline__ float2 upk2(ull u) {
    float2 f; memcpy(&f, &u, 8); return f;
}
__device__ __forceinline__ float wredsum(float v) {
    #pragma unroll
    for (int o = 16; o; o >>= 1) v += __shfl_down_sync(0xffffffffu, v, o);
    return v;
}
__device__ __forceinline__ float wredmax(float v) {
    #pragma unroll
    for (int o = 16; o; o >>= 1) v = fmaxf(v, __shfl_down_sync(0xffffffffu, v, o));
    return v;
}
__device__ __forceinline__ float blockSum(float v, float* red) {
    int lane = threadIdx.x & 31, wid = threadIdx.x >> 5, nw = blockDim.x >> 5;
    v = wredsum(v);
    __syncthreads();
    if (lane == 0) red[wid] = v;
    __syncthreads();
    if (wid == 0) {
        float r = (lane < nw) ? red[lane] : 0.f;
        r = wredsum(r);
        if (lane == 0) red[0] = r;
    }
    __syncthreads();
    return red[0];
}
__device__ __forceinline__ float blockMax(float v, float* red) {
    int lane = threadIdx.x & 31, wid = threadIdx.x >> 5, nw = blockDim.x >> 5;
    v = wredmax(v);
    __syncthreads();
    if (lane == 0) red[wid] = v;
    __syncthreads();
    if (wid == 0) {
        float r = (lane < nw) ? red[lane] : -1e30f;
        r = wredmax(r);
        if (lane == 0) red[0] = r;
    }
    __syncthreads();
    return red[0];
}
__device__ __forceinline__ float dot4(float4 a, float4 b) {
    return a.x*b.x + a.y*b.y + a.z*b.z + a.w*b.w;
}

// ---------------- K1: x = Wic @ [emb ; context] + bic ------------------------
__global__ void k_x(const float* __restrict__ etab, const int* __restrict__ ids,
                    const float* __restrict__ ctx,  const float* __restrict__ Wic,
                    const float* __restrict__ bic) {
    int w = (blockIdx.x * blockDim.x + threadIdx.x) >> 5;
    int lane = threadIdx.x & 31;
    int b = w >> 10, h = w & 1023;
    const float4* er = (const float4*)(etab + (long)ids[b] * E_);
    const float4* cr = (const float4*)(ctx + b * H_);
    const float4* wr = (const float4*)(Wic + (long)h * EH_);
    float acc = 0.f;
    #pragma unroll 4
    for (int k = lane; k < E_/4; k += 32) acc += dot4(er[k], wr[k]);
    #pragma unroll 4
    for (int k = lane; k < H_/4; k += 32) acc += dot4(cr[k], wr[E_/4 + k]);
    acc = wredsum(acc);
    if (lane == 0) g_x[w] = acc + bic[h];
}

// ---------------- K2: GRUCell (r,z,n order), writes h_new --------------------
__global__ void k_gru(const float* __restrict__ hidden, const float* __restrict__ Wih,
                      const float* __restrict__ Whh,    const float* __restrict__ bih,
                      const float* __restrict__ bhh,    float* __restrict__ hnew) {
    int w = (blockIdx.x * blockDim.x + threadIdx.x) >> 5;
    int lane = threadIdx.x & 31;
    int b = w >> 10, i = w & 1023;
    const float4* xr = (const float4*)(g_x + b * H_);
    const float4* hr = (const float4*)(hidden + b * H_);
    const float4* w0 = (const float4*)(Wih + (long)i * H_);
    const float4* w1 = (const float4*)(Wih + (long)(i + H_) * H_);
    const float4* w2 = (const float4*)(Wih + (long)(i + 2*H_) * H_);
    const float4* u0 = (const float4*)(Whh + (long)i * H_);
    const float4* u1 = (const float4*)(Whh + (long)(i + H_) * H_);
    const float4* u2 = (const float4*)(Whh + (long)(i + 2*H_) * H_);
    float ir = 0, iz = 0, inn = 0, hrr = 0, hz = 0, hn = 0;
    for (int k = lane; k < H_/4; k += 32) {
        float4 xv = xr[k], hv = hr[k];
        ir  += dot4(xv, w0[k]);  iz += dot4(xv, w1[k]);  inn += dot4(xv, w2[k]);
        hrr += dot4(hv, u0[k]);  hz += dot4(hv, u1[k]);  hn  += dot4(hv, u2[k]);
    }
    ir = wredsum(ir);  iz = wredsum(iz);  inn = wredsum(inn);
    hrr = wredsum(hrr); hz = wredsum(hz); hn = wredsum(hn);
    if (lane == 0) {
        float r = 1.f / (1.f + expf(-(ir + bih[i] + hrr + bhh[i])));
        float z = 1.f / (1.f + expf(-(iz + bih[i + H_] + hz + bhh[i + H_])));
        float n = tanhf(inn + bih[i + 2*H_] + r * (hn + bhh[i + 2*H_]));
        hnew[b * H_ + i] = (1.f - z) * n + z * hidden[b * H_ + i];
    }
}

// ---------------- K3: base = Wah@h_new + bah + bas + bac ---------------------
__global__ void k_base(const float* __restrict__ hnew, const float* __restrict__ Wah,
                       const float* __restrict__ bah,  const float* __restrict__ bas,
                       const float* __restrict__ bac) {
    int w = (blockIdx.x * blockDim.x + threadIdx.x) >> 5;
    int lane = threadIdx.x & 31;
    int b = w >> 10, g = w & 1023;
    const float4* hr = (const float4*)(hnew + b * H_);
    const float4* wr = (const float4*)(Wah + (long)g * H_);
    float acc = 0.f;
    #pragma unroll 4
    for (int k = lane; k < H_/4; k += 32) acc += dot4(hr[k], wr[k]);
    acc = wredsum(acc);
    if (lane == 0) g_base[w] = acc + bah[g] + bas[g] + bac[g];
}

// ---------------- K4: BIG fused attention-score GEMM -------------------------
// scores[b,s] = bsq + sum_g Wsq[g]*tanh( (ss[s,b,:]@Was[g,:]) + base[b,g] + cov[b,s]*Wac[g] )
#define R4 32
#define C4 128
#define KT 32
__global__ __launch_bounds__(256) void k_scores(
    const float* __restrict__ ss,  const float* __restrict__ Was,
    const float* __restrict__ cov, const float* __restrict__ wac,
    const float* __restrict__ wsq, const float* __restrict__ bsq) {
    __shared__ float ssm[R4][KT];         // 4 KB
    __shared__ float wsm[KT][C4 + 4];     // 16.5 KB
    int tid = threadIdx.x;
    int tx = tid & 15, ty = tid >> 4;
    int b = blockIdx.y;
    int s0 = blockIdx.x * R4;
    int lr = tid >> 3, lk4 = tid & 7;     // ss-tile loader
    int lc = tid >> 1, lh = tid & 1;      // Was-tile loader

    float covA = cov[b * S_ + s0 + ty];
    float covB = cov[b * S_ + s0 + ty + 16];
    float scoreA = 0.f, scoreB = 0.f;

    for (int ch = 0; ch < H_; ch += C4) {
        ull a0, a1, a2, a3, c0_, c1_, c2_, c3_;
        a0 = a1 = a2 = a3 = c0_ = c1_ = c2_ = c3_ = pk2(0.f, 0.f);
        for (int k0 = 0; k0 < H_; k0 += KT) {
            __syncthreads();
            *(float4*)&ssm[lr][lk4 * 4] =
                *(const float4*)&ss[((long)(s0 + lr) * B_ + b) * H_ + k0 + lk4 * 4];
            {
                const float4* src = (const float4*)&Was[(long)(ch + lc) * H_ + k0 + lh * 16];
                #pragma unroll
                for (int q = 0; q < 4; q++) {
                    float4 v = src[q];
                    int kk = lh * 16 + q * 4;
                    wsm[kk + 0][lc] = v.x; wsm[kk + 1][lc] = v.y;
                    wsm[kk + 2][lc] = v.z; wsm[kk + 3][lc] = v.w;
                }
            }
            __syncthreads();
            #pragma unroll
            for (int k = 0; k < KT; k++) {
                float sa = ssm[ty][k], sb = ssm[ty + 16][k];
                ull saa = pk2(sa, sa), sbb = pk2(sb, sb);
                const ull* wp = (const ull*)&wsm[k][tx * 8];
                ull w0 = wp[0], w1 = wp[1], w2 = wp[2], w3 = wp[3];
                ffma2(a0, saa, w0); ffma2(a1, saa, w1);
                ffma2(a2, saa, w2); ffma2(a3, saa, w3);
                ffma2(c0_, sbb, w0); ffma2(c1_, sbb, w1);
                ffma2(c2_, sbb, w2); ffma2(c3_, sbb, w3);
            }
        }
        int cb = ch + tx * 8;
        #define EPI(AJ, BJ, J) { \
            float2 fa = upk2(AJ), fb = upk2(BJ); \
            int cc = cb + 2 * (J); \
            float bs0 = g_base[b*H_ + cc],     wa0 = wac[cc],     q0 = wsq[cc]; \
            float bs1 = g_base[b*H_ + cc + 1], wa1 = wac[cc + 1], q1 = wsq[cc + 1]; \
            scoreA += q0 * tanhf(fa.x + bs0 + covA * wa0) + q1 * tanhf(fa.y + bs1 + covA * wa1); \
            scoreB += q0 * tanhf(fb.x + bs0 + covB * wa0) + q1 * tanhf(fb.y + bs1 + covB * wa1); }
        EPI(a0, c0_, 0) EPI(a1, c1_, 1) EPI(a2, c2_, 2) EPI(a3, c3_, 3)
        #undef EPI
    }
    #pragma unroll
    for (int o = 8; o; o >>= 1) {
        scoreA += __shfl_down_sync(0xffffffffu, scoreA, o, 16);
        scoreB += __shfl_down_sync(0xffffffffu, scoreB, o, 16);
    }
    if (tx == 0) {
        float bq = bsq[0];
        g_scores[b * S_ + s0 + ty]      = scoreA + bq;
        g_scores[b * S_ + s0 + ty + 16] = scoreB + bq;
    }
}

// ---------------- K5: attention softmax chain + coverage ---------------------
__global__ void k_attnsm(const float* __restrict__ coverage, const int* __restrict__ story,
                         float* __restrict__ out) {
    __shared__ float red[32];
    int b = blockIdx.x, t = threadIdx.x;
    float sc = g_scores[b * S_ + t];
    float m = (story[b * S_ + t] > 0) ? 1.f : 0.f;
    float mx = blockMax(sc, red);
    float e = expf(sc - mx);
    float sum = blockSum(e, red);
    float p = (e / sum) * m;
    float s2 = blockSum(p, red);
    float attn = p / s2;
    g_attn[b * S_ + t] = attn;
    out[OFF_COV + b * S_ + t] = coverage[b * S_ + t] + attn;
    float mx2 = blockMax(attn, red);
    float e2 = expf(attn - mx2);
    float s3 = blockSum(e2, red);
    out[OFF_ATTN + b * S_ + t] = e2 / s3;
}

// ---------------- K6: ctx = attn @ story_states ------------------------------
__global__ void k_ctx(const float* __restrict__ ss, float* __restrict__ out) {
    __shared__ float sa[S_];
    int b = blockIdx.y;
    int h = blockIdx.x * 256 + threadIdx.x;
    for (int i = threadIdx.x; i < S_; i += 256) sa[i] = g_attn[b * S_ + i];
    __syncthreads();
    float acc = 0.f;
    #pragma unroll 8
    for (int s = 0; s < S_; s++) acc += sa[s] * ss[((long)s * B_ + b) * H_ + h];
    out[OFF_CTX + b * H_ + h] = acc;
}

// ---------------- K7: pointer-gen gate ---------------------------------------
__global__ void k_pgen(const float* __restrict__ Wpg, const float* __restrict__ bpg,
                       float* __restrict__ out) {
    __shared__ float red[32];
    int b = blockIdx.x, t = threadIdx.x;
    float acc = 0.f;
    for (int k = t; k < H_; k += 256)
        acc += (g_x[b*H_ + k] + out[OFF_CTX + b*H_ + k] + out[OFF_HNEW + b*H_ + k]) * Wpg[k];
    float s = blockSum(acc, red);
    if (t == 0) out[OFF_PGEN + b] = 1.f / (1.f + expf(-(s + bpg[0])));
}

// ---------------- K8: vocab logits GEMM [64 x 32000, K=2048] -----------------
__global__ __launch_bounds__(256) void k_logits(
    const float* __restrict__ hnew, const float* __restrict__ ctx,
    const float* __restrict__ Wout, const float* __restrict__ bout) {
    __shared__ float am[64][KT];         // 8 KB
    __shared__ float wsm[KT][C4 + 4];    // 16.5 KB
    int tid = threadIdx.x;
    int tx = tid & 15, ty = tid >> 4;
    int vc = blockIdx.x * C4;
    int lr = tid >> 2, lk8 = tid & 3;
    int lc = tid >> 1, lh = tid & 1;
    ull acc[4][4];
    #pragma unroll
    for (int r = 0; r < 4; r++)
        #pragma unroll
        for (int j = 0; j < 4; j++) acc[r][j] = pk2(0.f, 0.f);

    for (int k0 = 0; k0 < 2 * H_; k0 += KT) {
        __syncthreads();
        {
            const float* srcb = (k0 < H_) ? (hnew + lr * H_ + k0)
                                          : (ctx + lr * H_ + (k0 - H_));
            *(float4*)&am[lr][lk8 * 8]     = *(const float4*)(srcb + lk8 * 8);
            *(float4*)&am[lr][lk8 * 8 + 4] = *(const float4*)(srcb + lk8 * 8 + 4);
        }
        {
            const float4* src = (const float4*)&Wout[(long)(vc + lc) * (2*H_) + k0 + lh * 16];
            #pragma unroll
            for (int q = 0; q < 4; q++) {
                float4 v = src[q];
                int kk = lh * 16 + q * 4;
                wsm[kk + 0][lc] = v.x; wsm[kk + 1][lc] = v.y;
                wsm[kk + 2][lc] = v.z; wsm[kk + 3][lc] = v.w;
            }
        }
        __syncthreads();
        #pragma unroll
        for (int k = 0; k < KT; k++) {
            const ull* wp = (const ull*)&wsm[k][tx * 8];
            ull w0 = wp[0], w1 = wp[1], w2 = wp[2], w3 = wp[3];
            #pragma unroll
            for (int r = 0; r < 4; r++) {
                float av = am[ty + r * 16][k];
                ull aa = pk2(av, av);
                ffma2(acc[r][0], aa, w0); ffma2(acc[r][1], aa, w1);
                ffma2(acc[r][2], aa, w2); ffma2(acc[r][3], aa, w3);
            }
        }
    }
    #pragma unroll
    for (int r = 0; r < 4; r++) {
        int brow = ty + r * 16;
        #pragma unroll
        for (int j = 0; j < 4; j++) {
            float2 f = upk2(acc[r][j]);
            int v = vc + tx * 8 + 2 * j;
            g_logits[(long)brow * V_ + v]     = f.x + bout[v];
            g_logits[(long)brow * V_ + v + 1] = f.y + bout[v + 1];
        }
    }
}

// ---------------- K9: vocab softmax ------------------------------------------
__global__ void k_vocabsm(float* __restrict__ out) {
    __shared__ float red[32];
    int b = blockIdx.x, t = threadIdx.x;
    const float* lg = g_logits + (long)b * V_;
    float* vo = out + OFF_VOCAB + (long)b * V_;
    float mx = -1e30f;
    for (int v = t; v < V_; v += 1024) mx = fmaxf(mx, lg[v]);
    mx = blockMax(mx, red);
    float sum = 0.f;
    for (int v = t; v < V_; v += 1024) { float e = expf(lg[v] - mx); vo[v] = e; sum += e; }
    sum = blockSum(sum, red);
    float inv = 1.f / sum;
    for (int v = t; v < V_; v += 1024) vo[v] *= inv;
}

// ---------------- launch ------------------------------------------------------
extern "C" void kernel_launch(void* const* d_in, const int* in_sizes, int n_in,
                              void* d_out, int out_size) {
    (void)in_sizes; (void)n_in; (void)out_size;
    const float* ss       = (const float*)d_in[0];
    const int*   story    = (const int*)  d_in[1];
    const int*   ids      = (const int*)  d_in[2];
    const float* hidden   = (const float*)d_in[3];
    const float* context  = (const float*)d_in[4];
    const float* coverage = (const float*)d_in[5];
    const float* etab     = (const float*)d_in[6];
    const float* Wic = (const float*)d_in[7];   const float* bic = (const float*)d_in[8];
    const float* Wah = (const float*)d_in[9];   const float* bah = (const float*)d_in[10];
    const float* Was = (const float*)d_in[11];  const float* bas = (const float*)d_in[12];
    const float* Wac = (const float*)d_in[13];  const float* bac = (const float*)d_in[14];
    const float* Wsq = (const float*)d_in[15];  const float* bsq = (const float*)d_in[16];
    const float* Wpg = (const float*)d_in[17];  const float* bpg = (const float*)d_in[18];
    const float* Wih = (const float*)d_in[19];  const float* Whh = (const float*)d_in[20];
    const float* bih = (const float*)d_in[21];  const float* bhh = (const float*)d_in[22];
    const float* Wout = (const float*)d_in[23]; const float* bout = (const float*)d_in[24];
    float* out = (float*)d_out;
    float* hnew = out + OFF_HNEW;

    k_x  <<<B_*H_/8, 256>>>(etab, ids, context, Wic, bic);
    k_gru<<<B_*H_/8, 256>>>(hidden, Wih, Whh, bih, bhh, hnew);
    k_base<<<B_*H_/8, 256>>>(hnew, Wah, bah, bas, bac);
    k_scores<<<dim3(S_/R4, B_), 256>>>(ss, Was, coverage, Wac, Wsq, bsq);
    k_attnsm<<<B_, S_>>>(coverage, story, out);
    k_ctx<<<dim3(H_/256, B_), 256>>>(ss, out);
    k_pgen<<<B_, 256>>>(Wpg, bpg, out);
    k_logits<<<V_/C4, 256>>>(hnew, out + OFF_CTX, Wout, bout);
    k_vocabsm<<<B_, 1024>>>(out);
}

// round 7
// speedup vs baseline: 4.9049x; 4.9049x over previous
#include <cuda_runtime.h>
#include <cuda_bf16.h>
#include <cstring>
#include <math.h>
#include <stdint.h>

#define S_  1024
#define B_  64
#define H_  1024
#define E_  512
#define V_  32000
#define EH_ 1536

typedef unsigned long long ull;

// ---------------- scratch (device globals; no runtime allocation) -------------
__device__ float g_x[B_*H_];        // input-context projection x [B,H]
__device__ float g_base[B_*H_];     // Wah@h_new + bah + bas + bac  [B,H]
__device__ float g_scores[B_*S_];   // attention scores [B,S]
__device__ float g_attn[B_*S_];     // renormalized attention [B,S]
__device__ float g_logits[B_*V_];   // vocab logits (8 MB)

// ---------------- output layout (f32, concatenated in return order) ----------
#define OFF_PGEN  0
#define OFF_VOCAB 64
#define OFF_HNEW  (OFF_VOCAB + B_*V_)
#define OFF_CTX   (OFF_HNEW + B_*H_)
#define OFF_ATTN  (OFF_CTX  + B_*H_)
#define OFF_COV   (OFF_ATTN + B_*S_)

// ---------------- generic helpers --------------------------------------------
__device__ __forceinline__ void ffma2(ull& acc, ull a, ull b) {
    asm("fma.rn.f32x2 %0, %1, %2, %0;" : "+l"(acc) : "l"(a), "l"(b));
}
__device__ __forceinline__ ull pk2(float x, float y) {
    float2 f = make_float2(x, y); ull u; memcpy(&u, &f, 8); return u;
}
__device__ __forceinline__ float2 upk2(ull u) {
    float2 f; memcpy(&f, &u, 8); return f;
}
__device__ __forceinline__ float wredsum(float v) {
    #pragma unroll
    for (int o = 16; o; o >>= 1) v += __shfl_down_sync(0xffffffffu, v, o);
    return v;
}
__device__ __forceinline__ float wredmax(float v) {
    #pragma unroll
    for (int o = 16; o; o >>= 1) v = fmaxf(v, __shfl_down_sync(0xffffffffu, v, o));
    return v;
}
__device__ __forceinline__ float blockSum(float v, float* red) {
    int lane = threadIdx.x & 31, wid = threadIdx.x >> 5, nw = blockDim.x >> 5;
    v = wredsum(v);
    __syncthreads();
    if (lane == 0) red[wid] = v;
    __syncthreads();
    if (wid == 0) {
        float r = (lane < nw) ? red[lane] : 0.f;
        r = wredsum(r);
        if (lane == 0) red[0] = r;
    }
    __syncthreads();
    return red[0];
}
__device__ __forceinline__ float blockMax(float v, float* red) {
    int lane = threadIdx.x & 31, wid = threadIdx.x >> 5, nw = blockDim.x >> 5;
    v = wredmax(v);
    __syncthreads();
    if (lane == 0) red[wid] = v;
    __syncthreads();
    if (wid == 0) {
        float r = (lane < nw) ? red[lane] : -1e30f;
        r = wredmax(r);
        if (lane == 0) red[0] = r;
    }
    __syncthreads();
    return red[0];
}
__device__ __forceinline__ float dot4(float4 a, float4 b) {
    return a.x*b.x + a.y*b.y + a.z*b.z + a.w*b.w;
}
__device__ __forceinline__ uint32_t smem_to_u32(const void* p) {
    uint32_t a;
    asm("{ .reg .u64 t; cvta.to.shared.u64 t, %1; cvt.u32.u64 %0, t; }"
        : "=r"(a) : "l"(p));
    return a;
}

// ---------------- HMMA helpers ------------------------------------------------
#define LDSM4(R, addr) \
    asm volatile("ldmatrix.sync.aligned.m8n8.x4.shared.b16 {%0,%1,%2,%3}, [%4];" \
        : "=r"((R)[0]), "=r"((R)[1]), "=r"((R)[2]), "=r"((R)[3]) : "r"(addr))

#define MMA16816(D, A, Bp) \
    asm volatile("mma.sync.aligned.m16n8k16.row.col.f32.bf16.bf16.f32 " \
        "{%0,%1,%2,%3}, {%4,%5,%6,%7}, {%8,%9}, {%0,%1,%2,%3};" \
        : "+f"((D)[0]), "+f"((D)[1]), "+f"((D)[2]), "+f"((D)[3]) \
        : "r"((A)[0]), "r"((A)[1]), "r"((A)[2]), "r"((A)[3]), \
          "r"((Bp)[0]), "r"((Bp)[1]))

// bf16 split: v = hi + lo (both bf16)
__device__ __forceinline__ void bfsplit(float v, unsigned short& h, unsigned short& l) {
    __nv_bfloat16 hh = __float2bfloat16_rn(v);
    float r = v - __bfloat162float(hh);
    __nv_bfloat16 ll = __float2bfloat16_rn(r);
    h = *reinterpret_cast<unsigned short*>(&hh);
    l = *reinterpret_cast<unsigned short*>(&ll);
}

// ---------------- K1: x = Wic @ [emb ; context] + bic ------------------------
__global__ void k_x(const float* __restrict__ etab, const int* __restrict__ ids,
                    const float* __restrict__ ctx,  const float* __restrict__ Wic,
                    const float* __restrict__ bic) {
    int w = (blockIdx.x * blockDim.x + threadIdx.x) >> 5;
    int lane = threadIdx.x & 31;
    int b = w >> 10, h = w & 1023;
    const float4* er = (const float4*)(etab + (long)ids[b] * E_);
    const float4* cr = (const float4*)(ctx + b * H_);
    const float4* wr = (const float4*)(Wic + (long)h * EH_);
    float acc = 0.f;
    #pragma unroll 4
    for (int k = lane; k < E_/4; k += 32) acc += dot4(er[k], wr[k]);
    #pragma unroll 4
    for (int k = lane; k < H_/4; k += 32) acc += dot4(cr[k], wr[E_/4 + k]);
    acc = wredsum(acc);
    if (lane == 0) g_x[w] = acc + bic[h];
}

// ---------------- K2: GRUCell (r,z,n order), writes h_new --------------------
__global__ void k_gru(const float* __restrict__ hidden, const float* __restrict__ Wih,
                      const float* __restrict__ Whh,    const float* __restrict__ bih,
                      const float* __restrict__ bhh,    float* __restrict__ hnew) {
    int w = (blockIdx.x * blockDim.x + threadIdx.x) >> 5;
    int lane = threadIdx.x & 31;
    int b = w >> 10, i = w & 1023;
    const float4* xr = (const float4*)(g_x + b * H_);
    const float4* hr = (const float4*)(hidden + b * H_);
    const float4* w0 = (const float4*)(Wih + (long)i * H_);
    const float4* w1 = (const float4*)(Wih + (long)(i + H_) * H_);
    const float4* w2 = (const float4*)(Wih + (long)(i + 2*H_) * H_);
    const float4* u0 = (const float4*)(Whh + (long)i * H_);
    const float4* u1 = (const float4*)(Whh + (long)(i + H_) * H_);
    const float4* u2 = (const float4*)(Whh + (long)(i + 2*H_) * H_);
    float ir = 0, iz = 0, inn = 0, hrr = 0, hz = 0, hn = 0;
    for (int k = lane; k < H_/4; k += 32) {
        float4 xv = xr[k], hv = hr[k];
        ir  += dot4(xv, w0[k]);  iz += dot4(xv, w1[k]);  inn += dot4(xv, w2[k]);
        hrr += dot4(hv, u0[k]);  hz += dot4(hv, u1[k]);  hn  += dot4(hv, u2[k]);
    }
    ir = wredsum(ir);  iz = wredsum(iz);  inn = wredsum(inn);
    hrr = wredsum(hrr); hz = wredsum(hz); hn = wredsum(hn);
    if (lane == 0) {
        float r = 1.f / (1.f + expf(-(ir + bih[i] + hrr + bhh[i])));
        float z = 1.f / (1.f + expf(-(iz + bih[i + H_] + hz + bhh[i + H_])));
        float n = tanhf(inn + bih[i + 2*H_] + r * (hn + bhh[i + 2*H_]));
        hnew[b * H_ + i] = (1.f - z) * n + z * hidden[b * H_ + i];
    }
}

// ---------------- K3: base = Wah@h_new + bah + bas + bac ---------------------
__global__ void k_base(const float* __restrict__ hnew, const float* __restrict__ Wah,
                       const float* __restrict__ bah,  const float* __restrict__ bas,
                       const float* __restrict__ bac) {
    int w = (blockIdx.x * blockDim.x + threadIdx.x) >> 5;
    int lane = threadIdx.x & 31;
    int b = w >> 10, g = w & 1023;
    const float4* hr = (const float4*)(hnew + b * H_);
    const float4* wr = (const float4*)(Wah + (long)g * H_);
    float acc = 0.f;
    #pragma unroll 4
    for (int k = lane; k < H_/4; k += 32) acc += dot4(hr[k], wr[k]);
    acc = wredsum(acc);
    if (lane == 0) g_base[w] = acc + bah[g] + bas[g] + bac[g];
}

// ---------------- K4: HMMA attention-score GEMM ------------------------------
// scores[b,s] = bsq + sum_g wsq[g]*tanh( ss[s,b,:]@Was[g,:] + base[b,g] + cov[b,s]*wac[g] )
// split-bf16 (hi+lo, 3 MMA terms) for ~fp32 accuracy on mma.sync.m16n8k16.bf16
#define ROWE 40              // smem row stride in bf16 elems (32 + 8 pad)
#define ROWB (ROWE*2)        // 80 bytes

__global__ __launch_bounds__(256, 2) void k_scores_mma(
    const float* __restrict__ ss,  const float* __restrict__ Was,
    const float* __restrict__ cov, const float* __restrict__ wac,
    const float* __restrict__ wsq, const float* __restrict__ bsq) {
    __shared__ __align__(16) unsigned short Ah[128*ROWE], Al[128*ROWE];
    __shared__ __align__(16) unsigned short Bh[128*ROWE], Bl[128*ROWE];
    __shared__ float red2[2][128];

    int tid = threadIdx.x, L = tid & 31, wid = tid >> 5;
    int wm = wid >> 1, wn = wid & 1;
    int b = blockIdx.y, s0 = blockIdx.x * 128;

    uint32_t uAh = smem_to_u32(Ah), uAl = smem_to_u32(Al);
    uint32_t uBh = smem_to_u32(Bh), uBl = smem_to_u32(Bl);

    // ldmatrix per-lane byte offsets within a 16x16 tile region
    uint32_t aoff = ((L & 7) + ((L >> 3) & 1) * 8) * ROWB + ((L >> 4) & 1) * 16;
    uint32_t boff = ((L & 7) + ((L >> 4) & 1) * 8) * ROWB + ((L >> 3) & 1) * 16;

    // coverage for the 4 rows this thread's accumulators touch
    float cov4[2][2];
    #pragma unroll
    for (int mt = 0; mt < 2; mt++)
        #pragma unroll
        for (int h = 0; h < 2; h++)
            cov4[mt][h] = cov[b * S_ + s0 + wm*32 + mt*16 + h*8 + (L >> 2)];

    float rs[2][2] = {{0.f, 0.f}, {0.f, 0.f}};

    for (int np = 0; np < 8; np++) {
        int n0 = np * 128;
        float c[2][8][4];
        #pragma unroll
        for (int mt = 0; mt < 2; mt++)
            #pragma unroll
            for (int nt = 0; nt < 8; nt++)
                #pragma unroll
                for (int j = 0; j < 4; j++) c[mt][nt][j] = 0.f;

        for (int kc = 0; kc < 32; kc++) {
            int k0 = kc * 32;
            __syncthreads();
            // load 128x32 f32 of A and B, split to bf16 hi/lo, store to smem
            #pragma unroll
            for (int j = 0; j < 4; j++) {
                int f = tid + j * 256;          // float4 index, 8 per row
                int row = f >> 3, q = f & 7;
                float4 v = *(const float4*)&ss[(((long)(s0 + row)) * B_ + b) * H_ + k0 + q*4];
                ushort4 hi, lo;
                bfsplit(v.x, hi.x, lo.x); bfsplit(v.y, hi.y, lo.y);
                bfsplit(v.z, hi.z, lo.z); bfsplit(v.w, hi.w, lo.w);
                *(ushort4*)&Ah[row * ROWE + q*4] = hi;
                *(ushort4*)&Al[row * ROWE + q*4] = lo;
                float4 w = *(const float4*)&Was[((long)(n0 + row)) * H_ + k0 + q*4];
                bfsplit(w.x, hi.x, lo.x); bfsplit(w.y, hi.y, lo.y);
                bfsplit(w.z, hi.z, lo.z); bfsplit(w.w, hi.w, lo.w);
                *(ushort4*)&Bh[row * ROWE + q*4] = hi;
                *(ushort4*)&Bl[row * ROWE + q*4] = lo;
            }
            __syncthreads();
            #pragma unroll
            for (int ks = 0; ks < 2; ks++) {
                uint32_t kb = ks * 32;          // byte offset of k-step (16 elems)
                uint32_t ah[2][4], al[2][4];
                #pragma unroll
                for (int mt = 0; mt < 2; mt++) {
                    uint32_t base = (wm*32 + mt*16) * ROWB + kb;
                    LDSM4(ah[mt], uAh + base + aoff);
                    LDSM4(al[mt], uAl + base + aoff);
                }
                #pragma unroll
                for (int p = 0; p < 4; p++) {
                    uint32_t bb = (wn*64 + p*16) * ROWB + kb + boff;
                    uint32_t bh[4], bl[4];
                    LDSM4(bh, uBh + bb);
                    LDSM4(bl, uBl + bb);
                    #pragma unroll
                    for (int mt = 0; mt < 2; mt++) {
                        #pragma unroll
                        for (int t = 0; t < 2; t++) {
                            MMA16816(c[mt][p*2 + t], ah[mt], bh + t*2);
                            MMA16816(c[mt][p*2 + t], ah[mt], bl + t*2);
                            MMA16816(c[mt][p*2 + t], al[mt], bh + t*2);
                        }
                    }
                }
            }
        }
        // fused epilogue for this 128-col slab
        #pragma unroll
        for (int mt = 0; mt < 2; mt++) {
            #pragma unroll
            for (int nt = 0; nt < 8; nt++) {
                int g = n0 + wn*64 + nt*8 + (L & 3) * 2;
                float q0 = wsq[g],  q1 = wsq[g + 1];
                float e0 = g_base[b*H_ + g], e1 = g_base[b*H_ + g + 1];
                float w0 = wac[g],  w1 = wac[g + 1];
                rs[mt][0] += q0 * tanhf(c[mt][nt][0] + e0 + cov4[mt][0] * w0)
                           + q1 * tanhf(c[mt][nt][1] + e1 + cov4[mt][0] * w1);
                rs[mt][1] += q0 * tanhf(c[mt][nt][2] + e0 + cov4[mt][1] * w0)
                           + q1 * tanhf(c[mt][nt][3] + e1 + cov4[mt][1] * w1);
            }
        }
    }
    // reduce across quad lanes, then across the 2 n-warps
    #pragma unroll
    for (int mt = 0; mt < 2; mt++)
        #pragma unroll
        for (int h = 0; h < 2; h++) {
            float v = rs[mt][h];
            v += __shfl_xor_sync(0xffffffffu, v, 1);
            v += __shfl_xor_sync(0xffffffffu, v, 2);
            rs[mt][h] = v;
        }
    __syncthreads();
    if ((L & 3) == 0) {
        #pragma unroll
        for (int mt = 0; mt < 2; mt++)
            #pragma unroll
            for (int h = 0; h < 2; h++)
                red2[wn][wm*32 + mt*16 + h*8 + (L >> 2)] = rs[mt][h];
    }
    __syncthreads();
    if (tid < 128)
        g_scores[b * S_ + s0 + tid] = red2[0][tid] + red2[1][tid] + bsq[0];
}

// ---------------- K5: attention softmax chain + coverage ---------------------
__global__ void k_attnsm(const float* __restrict__ coverage, const int* __restrict__ story,
                         float* __restrict__ out) {
    __shared__ float red[32];
    int b = blockIdx.x, t = threadIdx.x;
    float sc = g_scores[b * S_ + t];
    float m = (story[b * S_ + t] > 0) ? 1.f : 0.f;
    float mx = blockMax(sc, red);
    float e = expf(sc - mx);
    float sum = blockSum(e, red);
    float p = (e / sum) * m;
    float s2 = blockSum(p, red);
    float attn = p / s2;
    g_attn[b * S_ + t] = attn;
    out[OFF_COV + b * S_ + t] = coverage[b * S_ + t] + attn;
    float mx2 = blockMax(attn, red);
    float e2 = expf(attn - mx2);
    float s3 = blockSum(e2, red);
    out[OFF_ATTN + b * S_ + t] = e2 / s3;
}

// ---------------- K6: ctx = attn @ story_states ------------------------------
__global__ void k_ctx(const float* __restrict__ ss, float* __restrict__ out) {
    __shared__ float sa[S_];
    int b = blockIdx.y;
    int h = blockIdx.x * 256 + threadIdx.x;
    for (int i = threadIdx.x; i < S_; i += 256) sa[i] = g_attn[b * S_ + i];
    __syncthreads();
    float acc = 0.f;
    #pragma unroll 8
    for (int s = 0; s < S_; s++) acc += sa[s] * ss[((long)s * B_ + b) * H_ + h];
    out[OFF_CTX + b * H_ + h] = acc;
}

// ---------------- K7: pointer-gen gate ---------------------------------------
__global__ void k_pgen(const float* __restrict__ Wpg, const float* __restrict__ bpg,
                       float* __restrict__ out) {
    __shared__ float red[32];
    int b = blockIdx.x, t = threadIdx.x;
    float acc = 0.f;
    for (int k = t; k < H_; k += 256)
        acc += (g_x[b*H_ + k] + out[OFF_CTX + b*H_ + k] + out[OFF_HNEW + b*H_ + k]) * Wpg[k];
    float s = blockSum(acc, red);
    if (t == 0) out[OFF_PGEN + b] = 1.f / (1.f + expf(-(s + bpg[0])));
}

// ---------------- K8: vocab logits GEMM [64 x 32000, K=2048] -----------------
#define KT 32
#define C4 128
__global__ __launch_bounds__(256) void k_logits(
    const float* __restrict__ hnew, const float* __restrict__ ctx,
    const float* __restrict__ Wout, const float* __restrict__ bout) {
    __shared__ float am[64][KT];         // 8 KB
    __shared__ float wsm[KT][C4 + 4];    // 16.5 KB
    int tid = threadIdx.x;
    int tx = tid & 15, ty = tid >> 4;
    int vc = blockIdx.x * C4;
    int lr = tid >> 2, lk8 = tid & 3;
    int lc = tid >> 1, lh = tid & 1;
    ull acc[4][4];
    #pragma unroll
    for (int r = 0; r < 4; r++)
        #pragma unroll
        for (int j = 0; j < 4; j++) acc[r][j] = pk2(0.f, 0.f);

    for (int k0 = 0; k0 < 2 * H_; k0 += KT) {
        __syncthreads();
        {
            const float* srcb = (k0 < H_) ? (hnew + lr * H_ + k0)
                                          : (ctx + lr * H_ + (k0 - H_));
            *(float4*)&am[lr][lk8 * 8]     = *(const float4*)(srcb + lk8 * 8);
            *(float4*)&am[lr][lk8 * 8 + 4] = *(const float4*)(srcb + lk8 * 8 + 4);
        }
        {
            const float4* src = (const float4*)&Wout[(long)(vc + lc) * (2*H_) + k0 + lh * 16];
            #pragma unroll
            for (int q = 0; q < 4; q++) {
                float4 v = src[q];
                int kk = lh * 16 + q * 4;
                wsm[kk + 0][lc] = v.x; wsm[kk + 1][lc] = v.y;
                wsm[kk + 2][lc] = v.z; wsm[kk + 3][lc] = v.w;
            }
        }
        __syncthreads();
        #pragma unroll
        for (int k = 0; k < KT; k++) {
            const ull* wp = (const ull*)&wsm[k][tx * 8];
            ull w0 = wp[0], w1 = wp[1], w2 = wp[2], w3 = wp[3];
            #pragma unroll
            for (int r = 0; r < 4; r++) {
                float av = am[ty + r * 16][k];
                ull aa = pk2(av, av);
                ffma2(acc[r][0], aa, w0); ffma2(acc[r][1], aa, w1);
                ffma2(acc[r][2], aa, w2); ffma2(acc[r][3], aa, w3);
            }
        }
    }
    #pragma unroll
    for (int r = 0; r < 4; r++) {
        int brow = ty + r * 16;
        #pragma unroll
        for (int j = 0; j < 4; j++) {
            float2 f = upk2(acc[r][j]);
            int v = vc + tx * 8 + 2 * j;
            g_logits[(long)brow * V_ + v]     = f.x + bout[v];
            g_logits[(long)brow * V_ + v + 1] = f.y + bout[v + 1];
        }
    }
}

// ---------------- K9: vocab softmax ------------------------------------------
__global__ void k_vocabsm(float* __restrict__ out) {
    __shared__ float red[32];
    int b = blockIdx.x, t = threadIdx.x;
    const float* lg = g_logits + (long)b * V_;
    float* vo = out + OFF_VOCAB + (long)b * V_;
    float mx = -1e30f;
    for (int v = t; v < V_; v += 1024) mx = fmaxf(mx, lg[v]);
    mx = blockMax(mx, red);
    float sum = 0.f;
    for (int v = t; v < V_; v += 1024) { float e = expf(lg[v] - mx); vo[v] = e; sum += e; }
    sum = blockSum(sum, red);
    float inv = 1.f / sum;
    for (int v = t; v < V_; v += 1024) vo[v] *= inv;
}

// ---------------- launch ------------------------------------------------------
extern "C" void kernel_launch(void* const* d_in, const int* in_sizes, int n_in,
                              void* d_out, int out_size) {
    (void)in_sizes; (void)n_in; (void)out_size;
    const float* ss       = (const float*)d_in[0];
    const int*   story    = (const int*)  d_in[1];
    const int*   ids      = (const int*)  d_in[2];
    const float* hidden   = (const float*)d_in[3];
    const float* context  = (const float*)d_in[4];
    const float* coverage = (const float*)d_in[5];
    const float* etab     = (const float*)d_in[6];
    const float* Wic = (const float*)d_in[7];   const float* bic = (const float*)d_in[8];
    const float* Wah = (const float*)d_in[9];   const float* bah = (const float*)d_in[10];
    const float* Was = (const float*)d_in[11];  const float* bas = (const float*)d_in[12];
    const float* Wac = (const float*)d_in[13];  const float* bac = (const float*)d_in[14];
    const float* Wsq = (const float*)d_in[15];  const float* bsq = (const float*)d_in[16];
    const float* Wpg = (const float*)d_in[17];  const float* bpg = (const float*)d_in[18];
    const float* Wih = (const float*)d_in[19];  const float* Whh = (const float*)d_in[20];
    const float* bih = (const float*)d_in[21];  const float* bhh = (const float*)d_in[22];
    const float* Wout = (const float*)d_in[23]; const float* bout = (const float*)d_in[24];
    float* out = (float*)d_out;
    float* hnew = out + OFF_HNEW;

    k_x  <<<B_*H_/8, 256>>>(etab, ids, context, Wic, bic);
    k_gru<<<B_*H_/8, 256>>>(hidden, Wih, Whh, bih, bhh, hnew);
    k_base<<<B_*H_/8, 256>>>(hnew, Wah, bah, bas, bac);
    k_scores_mma<<<dim3(S_/128, B_), 256>>>(ss, Was, coverage, Wac, Wsq, bsq);
    k_attnsm<<<B_, S_>>>(coverage, story, out);
    k_ctx<<<dim3(H_/256, B_), 256>>>(ss, out);
    k_pgen<<<B_, 256>>>(Wpg, bpg, out);
    k_logits<<<V_/C4, 256>>>(hnew, out + OFF_CTX, Wout, bout);
    k_vocabsm<<<B_, 1024>>>(out);
}

// round 8
// speedup vs baseline: 4.9350x; 1.0061x over previous
#include <cuda_runtime.h>
#include <cuda_bf16.h>
#include <cstring>
#include <math.h>
#include <stdint.h>

#define S_  1024
#define B_  64
#define H_  1024
#define E_  512
#define V_  32000
#define EH_ 1536

typedef unsigned long long ull;

// ---------------- scratch (device globals; no runtime allocation) -------------
__device__ float g_x[B_*H_];
__device__ float g_base[B_*H_];
__device__ float g_scores[B_*S_];
__device__ float g_attn[B_*S_];
__device__ float g_logits[B_*V_];
// pre-converted split-bf16 operands for the attention GEMM
__device__ __nv_bfloat16 g_ah[S_*B_*H_];   // ss hi  (128 MB)
__device__ __nv_bfloat16 g_al[S_*B_*H_];   // ss lo  (128 MB)
__device__ __nv_bfloat16 g_wh[H_*H_];      // Was hi (2 MB)
__device__ __nv_bfloat16 g_wl[H_*H_];      // Was lo (2 MB)

// ---------------- output layout (f32, concatenated in return order) ----------
#define OFF_PGEN  0
#define OFF_VOCAB 64
#define OFF_HNEW  (OFF_VOCAB + B_*V_)
#define OFF_CTX   (OFF_HNEW + B_*H_)
#define OFF_ATTN  (OFF_CTX  + B_*H_)
#define OFF_COV   (OFF_ATTN + B_*S_)

// ---------------- generic helpers --------------------------------------------
__device__ __forceinline__ void ffma2(ull& acc, ull a, ull b) {
    asm("fma.rn.f32x2 %0, %1, %2, %0;" : "+l"(acc) : "l"(a), "l"(b));
}
__device__ __forceinline__ ull pk2(float x, float y) {
    float2 f = make_float2(x, y); ull u; memcpy(&u, &f, 8); return u;
}
__device__ __forceinline__ float2 upk2(ull u) {
    float2 f; memcpy(&f, &u, 8); return f;
}
__device__ __forceinline__ float wredsum(float v) {
    #pragma unroll
    for (int o = 16; o; o >>= 1) v += __shfl_down_sync(0xffffffffu, v, o);
    return v;
}
__device__ __forceinline__ float wredmax(float v) {
    #pragma unroll
    for (int o = 16; o; o >>= 1) v = fmaxf(v, __shfl_down_sync(0xffffffffu, v, o));
    return v;
}
__device__ __forceinline__ float blockSum(float v, float* red) {
    int lane = threadIdx.x & 31, wid = threadIdx.x >> 5, nw = blockDim.x >> 5;
    v = wredsum(v);
    __syncthreads();
    if (lane == 0) red[wid] = v;
    __syncthreads();
    if (wid == 0) {
        float r = (lane < nw) ? red[lane] : 0.f;
        r = wredsum(r);
        if (lane == 0) red[0] = r;
    }
    __syncthreads();
    return red[0];
}
__device__ __forceinline__ float blockMax(float v, float* red) {
    int lane = threadIdx.x & 31, wid = threadIdx.x >> 5, nw = blockDim.x >> 5;
    v = wredmax(v);
    __syncthreads();
    if (lane == 0) red[wid] = v;
    __syncthreads();
    if (wid == 0) {
        float r = (lane < nw) ? red[lane] : -1e30f;
        r = wredmax(r);
        if (lane == 0) red[0] = r;
    }
    __syncthreads();
    return red[0];
}
__device__ __forceinline__ float dot4(float4 a, float4 b) {
    return a.x*b.x + a.y*b.y + a.z*b.z + a.w*b.w;
}
__device__ __forceinline__ uint32_t smem_to_u32(const void* p) {
    uint32_t a;
    asm("{ .reg .u64 t; cvta.to.shared.u64 t, %1; cvt.u32.u64 %0, t; }"
        : "=r"(a) : "l"(p));
    return a;
}

// ---------------- HMMA / async-copy helpers -----------------------------------
#define LDSM4(R, addr) \
    asm volatile("ldmatrix.sync.aligned.m8n8.x4.shared.b16 {%0,%1,%2,%3}, [%4];" \
        : "=r"((R)[0]), "=r"((R)[1]), "=r"((R)[2]), "=r"((R)[3]) : "r"(addr))

#define MMA16816(D, A, Bp) \
    asm volatile("mma.sync.aligned.m16n8k16.row.col.f32.bf16.bf16.f32 " \
        "{%0,%1,%2,%3}, {%4,%5,%6,%7}, {%8,%9}, {%0,%1,%2,%3};" \
        : "+f"((D)[0]), "+f"((D)[1]), "+f"((D)[2]), "+f"((D)[3]) \
        : "r"((A)[0]), "r"((A)[1]), "r"((A)[2]), "r"((A)[3]), \
          "r"((Bp)[0]), "r"((Bp)[1]))

#define CPA16(dst, src) \
    asm volatile("cp.async.cg.shared.global [%0], [%1], 16;" \
        :: "r"(dst), "l"(src) : "memory")
#define CPA_COMMIT() asm volatile("cp.async.commit_group;" ::: "memory")
#define CPA_WAIT1()  asm volatile("cp.async.wait_group 1;" ::: "memory")
#define CPA_WAIT0()  asm volatile("cp.async.wait_group 0;" ::: "memory")

// bf16 split: v = hi + lo (both bf16)
__device__ __forceinline__ void bfsplit(float v, unsigned short& h, unsigned short& l) {
    __nv_bfloat16 hh = __float2bfloat16_rn(v);
    float r = v - __bfloat162float(hh);
    __nv_bfloat16 ll = __float2bfloat16_rn(r);
    h = *reinterpret_cast<unsigned short*>(&hh);
    l = *reinterpret_cast<unsigned short*>(&ll);
}

// ---------------- K0a/K0b: split-convert pre-passes ---------------------------
__global__ void k_cvt_ss(const float* __restrict__ src) {
    int i = blockIdx.x * blockDim.x + threadIdx.x;   // float4 index
    float4 v = ((const float4*)src)[i];
    ushort4 h, l;
    bfsplit(v.x, h.x, l.x); bfsplit(v.y, h.y, l.y);
    bfsplit(v.z, h.z, l.z); bfsplit(v.w, h.w, l.w);
    ((ushort4*)g_ah)[i] = h;
    ((ushort4*)g_al)[i] = l;
}
__global__ void k_cvt_was(const float* __restrict__ src) {
    int i = blockIdx.x * blockDim.x + threadIdx.x;
    float4 v = ((const float4*)src)[i];
    ushort4 h, l;
    bfsplit(v.x, h.x, l.x); bfsplit(v.y, h.y, l.y);
    bfsplit(v.z, h.z, l.z); bfsplit(v.w, h.w, l.w);
    ((ushort4*)g_wh)[i] = h;
    ((ushort4*)g_wl)[i] = l;
}

// ---------------- K1: x = Wic @ [emb ; context] + bic ------------------------
__global__ void k_x(const float* __restrict__ etab, const int* __restrict__ ids,
                    const float* __restrict__ ctx,  const float* __restrict__ Wic,
                    const float* __restrict__ bic) {
    int w = (blockIdx.x * blockDim.x + threadIdx.x) >> 5;
    int lane = threadIdx.x & 31;
    int b = w >> 10, h = w & 1023;
    const float4* er = (const float4*)(etab + (long)ids[b] * E_);
    const float4* cr = (const float4*)(ctx + b * H_);
    const float4* wr = (const float4*)(Wic + (long)h * EH_);
    float acc = 0.f;
    #pragma unroll 4
    for (int k = lane; k < E_/4; k += 32) acc += dot4(er[k], wr[k]);
    #pragma unroll 4
    for (int k = lane; k < H_/4; k += 32) acc += dot4(cr[k], wr[E_/4 + k]);
    acc = wredsum(acc);
    if (lane == 0) g_x[w] = acc + bic[h];
}

// ---------------- K2: GRUCell (r,z,n order), writes h_new --------------------
__global__ void k_gru(const float* __restrict__ hidden, const float* __restrict__ Wih,
                      const float* __restrict__ Whh,    const float* __restrict__ bih,
                      const float* __restrict__ bhh,    float* __restrict__ hnew) {
    int w = (blockIdx.x * blockDim.x + threadIdx.x) >> 5;
    int lane = threadIdx.x & 31;
    int b = w >> 10, i = w & 1023;
    const float4* xr = (const float4*)(g_x + b * H_);
    const float4* hr = (const float4*)(hidden + b * H_);
    const float4* w0 = (const float4*)(Wih + (long)i * H_);
    const float4* w1 = (const float4*)(Wih + (long)(i + H_) * H_);
    const float4* w2 = (const float4*)(Wih + (long)(i + 2*H_) * H_);
    const float4* u0 = (const float4*)(Whh + (long)i * H_);
    const float4* u1 = (const float4*)(Whh + (long)(i + H_) * H_);
    const float4* u2 = (const float4*)(Whh + (long)(i + 2*H_) * H_);
    float ir = 0, iz = 0, inn = 0, hrr = 0, hz = 0, hn = 0;
    for (int k = lane; k < H_/4; k += 32) {
        float4 xv = xr[k], hv = hr[k];
        ir  += dot4(xv, w0[k]);  iz += dot4(xv, w1[k]);  inn += dot4(xv, w2[k]);
        hrr += dot4(hv, u0[k]);  hz += dot4(hv, u1[k]);  hn  += dot4(hv, u2[k]);
    }
    ir = wredsum(ir);  iz = wredsum(iz);  inn = wredsum(inn);
    hrr = wredsum(hrr); hz = wredsum(hz); hn = wredsum(hn);
    if (lane == 0) {
        float r = 1.f / (1.f + expf(-(ir + bih[i] + hrr + bhh[i])));
        float z = 1.f / (1.f + expf(-(iz + bih[i + H_] + hz + bhh[i + H_])));
        float n = tanhf(inn + bih[i + 2*H_] + r * (hn + bhh[i + 2*H_]));
        hnew[b * H_ + i] = (1.f - z) * n + z * hidden[b * H_ + i];
    }
}

// ---------------- K3: base = Wah@h_new + bah + bas + bac ---------------------
__global__ void k_base(const float* __restrict__ hnew, const float* __restrict__ Wah,
                       const float* __restrict__ bah,  const float* __restrict__ bas,
                       const float* __restrict__ bac) {
    int w = (blockIdx.x * blockDim.x + threadIdx.x) >> 5;
    int lane = threadIdx.x & 31;
    int b = w >> 10, g = w & 1023;
    const float4* hr = (const float4*)(hnew + b * H_);
    const float4* wr = (const float4*)(Wah + (long)g * H_);
    float acc = 0.f;
    #pragma unroll 4
    for (int k = lane; k < H_/4; k += 32) acc += dot4(hr[k], wr[k]);
    acc = wredsum(acc);
    if (lane == 0) g_base[w] = acc + bah[g] + bas[g] + bac[g];
}

// ---------------- K4: HMMA attention-score GEMM (cp.async double-buffered) ---
#define ROWE 40              // smem row stride in bf16 elems (32 + 8 pad)
#define ROWB (ROWE*2)        // 80 bytes
#define ARRB (128*ROWB)      // 10240 bytes per operand tile
#define STAGE (4*ARRB)       // Ah,Al,Bh,Bl = 40960 bytes per stage
#define SMEM_SC (2*STAGE + 1024)

// copy one K-chunk stage: 4 operand tiles of 128 rows x 32 bf16
__device__ __forceinline__ void sc_copy(uint32_t sb, int buf, int b, int s0,
                                        int n0, int k0, int tid) {
    int t64 = tid & 63, arr = tid >> 6;
    uint32_t dbase = sb + buf * STAGE + arr * ARRB;
    const __nv_bfloat16* gsrc;
    long rstride;
    if (arr == 0)      { gsrc = g_ah + ((long)s0 * B_ + b) * H_ + k0; rstride = (long)B_ * H_; }
    else if (arr == 1) { gsrc = g_al + ((long)s0 * B_ + b) * H_ + k0; rstride = (long)B_ * H_; }
    else if (arr == 2) { gsrc = g_wh + (long)n0 * H_ + k0;            rstride = H_; }
    else               { gsrc = g_wl + (long)n0 * H_ + k0;            rstride = H_; }
    #pragma unroll
    for (int j = 0; j < 8; j++) {
        int c = j * 64 + t64;            // 512 16B-chunks per operand tile
        int row = c >> 2, q = c & 3;
        CPA16(dbase + row * ROWB + q * 16, (const char*)(gsrc + row * rstride) + q * 16);
    }
}

__global__ __launch_bounds__(256, 2) void k_scores_mma(
    const float* __restrict__ cov, const float* __restrict__ wac,
    const float* __restrict__ wsq, const float* __restrict__ bsq) {
    extern __shared__ __align__(16) char sm[];
    uint32_t sb = smem_to_u32(sm);
    float* red2 = (float*)(sm + 2 * STAGE);

    int tid = threadIdx.x, L = tid & 31, wid = tid >> 5;
    int wm = wid >> 1, wn = wid & 1;
    int b = blockIdx.y, s0 = blockIdx.x * 128;

    uint32_t aoff = ((L & 7) + ((L >> 3) & 1) * 8) * ROWB + ((L >> 4) & 1) * 16;
    uint32_t boff = ((L & 7) + ((L >> 4) & 1) * 8) * ROWB + ((L >> 3) & 1) * 16;

    float cov4[2][2];
    #pragma unroll
    for (int mt = 0; mt < 2; mt++)
        #pragma unroll
        for (int h = 0; h < 2; h++)
            cov4[mt][h] = cov[b * S_ + s0 + wm*32 + mt*16 + h*8 + (L >> 2)];

    float rs[2][2] = {{0.f, 0.f}, {0.f, 0.f}};

    // prologue: prefetch (np=0, kc=0) into buffer 0
    sc_copy(sb, 0, b, s0, 0, 0, tid);
    CPA_COMMIT();

    for (int np = 0; np < 8; np++) {
        int n0 = np * 128;
        float c[2][8][4];
        #pragma unroll
        for (int mt = 0; mt < 2; mt++)
            #pragma unroll
            for (int nt = 0; nt < 8; nt++)
                #pragma unroll
                for (int j = 0; j < 4; j++) c[mt][nt][j] = 0.f;

        for (int kc = 0; kc < 32; kc++) {
            if (kc < 31) {
                sc_copy(sb, (kc + 1) & 1, b, s0, n0, (kc + 1) * 32, tid);
                CPA_COMMIT();
                CPA_WAIT1();
            } else {
                CPA_WAIT0();
            }
            __syncthreads();
            uint32_t st = sb + (kc & 1) * STAGE;
            uint32_t uAh = st, uAl = st + ARRB, uBh = st + 2*ARRB, uBl = st + 3*ARRB;
            #pragma unroll
            for (int ks = 0; ks < 2; ks++) {
                uint32_t kb = ks * 32;
                uint32_t ah[2][4], al[2][4];
                #pragma unroll
                for (int mt = 0; mt < 2; mt++) {
                    uint32_t base = (wm*32 + mt*16) * ROWB + kb;
                    LDSM4(ah[mt], uAh + base + aoff);
                    LDSM4(al[mt], uAl + base + aoff);
                }
                #pragma unroll
                for (int p = 0; p < 4; p++) {
                    uint32_t bb = (wn*64 + p*16) * ROWB + kb + boff;
                    uint32_t bh[4], bl[4];
                    LDSM4(bh, uBh + bb);
                    LDSM4(bl, uBl + bb);
                    #pragma unroll
                    for (int mt = 0; mt < 2; mt++) {
                        #pragma unroll
                        for (int t = 0; t < 2; t++) {
                            MMA16816(c[mt][p*2 + t], ah[mt], bh + t*2);
                            MMA16816(c[mt][p*2 + t], ah[mt], bl + t*2);
                            MMA16816(c[mt][p*2 + t], al[mt], bh + t*2);
                        }
                    }
                }
            }
            __syncthreads();
        }
        // prefetch next n-chunk while the epilogue runs (smem buffer 0 is free)
        if (np < 7) {
            sc_copy(sb, 0, b, s0, n0 + 128, 0, tid);
            CPA_COMMIT();
        }
        // fused epilogue for this 128-col slab
        #pragma unroll
        for (int mt = 0; mt < 2; mt++) {
            #pragma unroll
            for (int nt = 0; nt < 8; nt++) {
                int g = n0 + wn*64 + nt*8 + (L & 3) * 2;
                float q0 = wsq[g],  q1 = wsq[g + 1];
                float e0 = g_base[b*H_ + g], e1 = g_base[b*H_ + g + 1];
                float w0 = wac[g],  w1 = wac[g + 1];
                rs[mt][0] += q0 * tanhf(c[mt][nt][0] + e0 + cov4[mt][0] * w0)
                           + q1 * tanhf(c[mt][nt][1] + e1 + cov4[mt][0] * w1);
                rs[mt][1] += q0 * tanhf(c[mt][nt][2] + e0 + cov4[mt][1] * w0)
                           + q1 * tanhf(c[mt][nt][3] + e1 + cov4[mt][1] * w1);
            }
        }
    }
    #pragma unroll
    for (int mt = 0; mt < 2; mt++)
        #pragma unroll
        for (int h = 0; h < 2; h++) {
            float v = rs[mt][h];
            v += __shfl_xor_sync(0xffffffffu, v, 1);
            v += __shfl_xor_sync(0xffffffffu, v, 2);
            rs[mt][h] = v;
        }
    __syncthreads();
    if ((L & 3) == 0) {
        #pragma unroll
        for (int mt = 0; mt < 2; mt++)
            #pragma unroll
            for (int h = 0; h < 2; h++)
                red2[wn*128 + wm*32 + mt*16 + h*8 + (L >> 2)] = rs[mt][h];
    }
    __syncthreads();
    if (tid < 128)
        g_scores[b * S_ + s0 + tid] = red2[tid] + red2[128 + tid] + bsq[0];
}

// ---------------- K5: attention softmax chain + coverage ---------------------
__global__ void k_attnsm(const float* __restrict__ coverage, const int* __restrict__ story,
                         float* __restrict__ out) {
    __shared__ float red[32];
    int b = blockIdx.x, t = threadIdx.x;
    float sc = g_scores[b * S_ + t];
    float m = (story[b * S_ + t] > 0) ? 1.f : 0.f;
    float mx = blockMax(sc, red);
    float e = expf(sc - mx);
    float sum = blockSum(e, red);
    float p = (e / sum) * m;
    float s2 = blockSum(p, red);
    float attn = p / s2;
    g_attn[b * S_ + t] = attn;
    out[OFF_COV + b * S_ + t] = coverage[b * S_ + t] + attn;
    float mx2 = blockMax(attn, red);
    float e2 = expf(attn - mx2);
    float s3 = blockSum(e2, red);
    out[OFF_ATTN + b * S_ + t] = e2 / s3;
}

// ---------------- K6: ctx = attn @ story_states ------------------------------
__global__ void k_ctx(const float* __restrict__ ss, float* __restrict__ out) {
    __shared__ float sa[S_];
    int b = blockIdx.y;
    int h = blockIdx.x * 256 + threadIdx.x;
    for (int i = threadIdx.x; i < S_; i += 256) sa[i] = g_attn[b * S_ + i];
    __syncthreads();
    float acc = 0.f;
    #pragma unroll 8
    for (int s = 0; s < S_; s++) acc += sa[s] * ss[((long)s * B_ + b) * H_ + h];
    out[OFF_CTX + b * H_ + h] = acc;
}

// ---------------- K7: pointer-gen gate ---------------------------------------
__global__ void k_pgen(const float* __restrict__ Wpg, const float* __restrict__ bpg,
                       float* __restrict__ out) {
    __shared__ float red[32];
    int b = blockIdx.x, t = threadIdx.x;
    float acc = 0.f;
    for (int k = t; k < H_; k += 256)
        acc += (g_x[b*H_ + k] + out[OFF_CTX + b*H_ + k] + out[OFF_HNEW + b*H_ + k]) * Wpg[k];
    float s = blockSum(acc, red);
    if (t == 0) out[OFF_PGEN + b] = 1.f / (1.f + expf(-(s + bpg[0])));
}

// ---------------- K8: vocab logits GEMM [64 x 32000, K=2048] -----------------
#define KT 32
#define C4 128
__global__ __launch_bounds__(256) void k_logits(
    const float* __restrict__ hnew, const float* __restrict__ ctx,
    const float* __restrict__ Wout, const float* __restrict__ bout) {
    __shared__ float am[64][KT];
    __shared__ float wsm[KT][C4 + 4];
    int tid = threadIdx.x;
    int tx = tid & 15, ty = tid >> 4;
    int vc = blockIdx.x * C4;
    int lr = tid >> 2, lk8 = tid & 3;
    int lc = tid >> 1, lh = tid & 1;
    ull acc[4][4];
    #pragma unroll
    for (int r = 0; r < 4; r++)
        #pragma unroll
        for (int j = 0; j < 4; j++) acc[r][j] = pk2(0.f, 0.f);

    for (int k0 = 0; k0 < 2 * H_; k0 += KT) {
        __syncthreads();
        {
            const float* srcb = (k0 < H_) ? (hnew + lr * H_ + k0)
                                          : (ctx + lr * H_ + (k0 - H_));
            *(float4*)&am[lr][lk8 * 8]     = *(const float4*)(srcb + lk8 * 8);
            *(float4*)&am[lr][lk8 * 8 + 4] = *(const float4*)(srcb + lk8 * 8 + 4);
        }
        {
            const float4* src = (const float4*)&Wout[(long)(vc + lc) * (2*H_) + k0 + lh * 16];
            #pragma unroll
            for (int q = 0; q < 4; q++) {
                float4 v = src[q];
                int kk = lh * 16 + q * 4;
                wsm[kk + 0][lc] = v.x; wsm[kk + 1][lc] = v.y;
                wsm[kk + 2][lc] = v.z; wsm[kk + 3][lc] = v.w;
            }
        }
        __syncthreads();
        #pragma unroll
        for (int k = 0; k < KT; k++) {
            const ull* wp = (const ull*)&wsm[k][tx * 8];
            ull w0 = wp[0], w1 = wp[1], w2 = wp[2], w3 = wp[3];
            #pragma unroll
            for (int r = 0; r < 4; r++) {
                float av = am[ty + r * 16][k];
                ull aa = pk2(av, av);
                ffma2(acc[r][0], aa, w0); ffma2(acc[r][1], aa, w1);
                ffma2(acc[r][2], aa, w2); ffma2(acc[r][3], aa, w3);
            }
        }
    }
    #pragma unroll
    for (int r = 0; r < 4; r++) {
        int brow = ty + r * 16;
        #pragma unroll
        for (int j = 0; j < 4; j++) {
            float2 f = upk2(acc[r][j]);
            int v = vc + tx * 8 + 2 * j;
            g_logits[(long)brow * V_ + v]     = f.x + bout[v];
            g_logits[(long)brow * V_ + v + 1] = f.y + bout[v + 1];
        }
    }
}

// ---------------- K9: vocab softmax ------------------------------------------
__global__ void k_vocabsm(float* __restrict__ out) {
    __shared__ float red[32];
    int b = blockIdx.x, t = threadIdx.x;
    const float* lg = g_logits + (long)b * V_;
    float* vo = out + OFF_VOCAB + (long)b * V_;
    float mx = -1e30f;
    for (int v = t; v < V_; v += 1024) mx = fmaxf(mx, lg[v]);
    mx = blockMax(mx, red);
    float sum = 0.f;
    for (int v = t; v < V_; v += 1024) { float e = expf(lg[v] - mx); vo[v] = e; sum += e; }
    sum = blockSum(sum, red);
    float inv = 1.f / sum;
    for (int v = t; v < V_; v += 1024) vo[v] *= inv;
}

// ---------------- launch ------------------------------------------------------
extern "C" void kernel_launch(void* const* d_in, const int* in_sizes, int n_in,
                              void* d_out, int out_size) {
    (void)in_sizes; (void)n_in; (void)out_size;
    const float* ss       = (const float*)d_in[0];
    const int*   story    = (const int*)  d_in[1];
    const int*   ids      = (const int*)  d_in[2];
    const float* hidden   = (const float*)d_in[3];
    const float* context  = (const float*)d_in[4];
    const float* coverage = (const float*)d_in[5];
    const float* etab     = (const float*)d_in[6];
    const float* Wic = (const float*)d_in[7];   const float* bic = (const float*)d_in[8];
    const float* Wah = (const float*)d_in[9];   const float* bah = (const float*)d_in[10];
    const float* Was = (const float*)d_in[11];  const float* bas = (const float*)d_in[12];
    const float* Wac = (const float*)d_in[13];  const float* bac = (const float*)d_in[14];
    const float* Wsq = (const float*)d_in[15];  const float* bsq = (const float*)d_in[16];
    const float* Wpg = (const float*)d_in[17];  const float* bpg = (const float*)d_in[18];
    const float* Wih = (const float*)d_in[19];  const float* Whh = (const float*)d_in[20];
    const float* bih = (const float*)d_in[21];  const float* bhh = (const float*)d_in[22];
    const float* Wout = (const float*)d_in[23]; const float* bout = (const float*)d_in[24];
    float* out = (float*)d_out;
    float* hnew = out + OFF_HNEW;

    static int smem_set = 0;
    if (!smem_set) {
        cudaFuncSetAttribute(k_scores_mma, cudaFuncAttributeMaxDynamicSharedMemorySize, SMEM_SC);
        smem_set = 1;
    }

    k_cvt_ss <<<(S_*B_*H_/4)/256, 256>>>(ss);
    k_cvt_was<<<(H_*H_/4)/256, 256>>>(Was);
    k_x  <<<B_*H_/8, 256>>>(etab, ids, context, Wic, bic);
    k_gru<<<B_*H_/8, 256>>>(hidden, Wih, Whh, bih, bhh, hnew);
    k_base<<<B_*H_/8, 256>>>(hnew, Wah, bah, bas, bac);
    k_scores_mma<<<dim3(S_/128, B_), 256, SMEM_SC>>>(coverage, Wac, Wsq, bsq);
    k_attnsm<<<B_, S_>>>(coverage, story, out);
    k_ctx<<<dim3(H_/256, B_), 256>>>(ss, out);
    k_pgen<<<B_, 256>>>(Wpg, bpg, out);
    k_logits<<<V_/C4, 256>>>(hnew, out + OFF_CTX, Wout, bout);
    k_vocabsm<<<B_, 1024>>>(out);
}